// round 17
// baseline (speedup 1.0000x reference)
#include <cuda_runtime.h>
#include <cuda_fp16.h>
#include <math.h>
#include <stdint.h>

// Problem constants
#define Bb   1024
#define Uu   8
#define Ss   50
#define Ll   200
#define Ff   4
#define Ee   32
#define Dd   128      // F*E
#define UE   256      // U*E
#define G4   512      // 4*D
#define NEGV -1000000000.0f

// ---------------- scratch (static device globals) ---------------------------
__device__ float  g_user_e[Bb * UE];          // (B,256) fp32 (longterm)
__device__ __half g_gateAh[Bb * G4];          // [user|short|long] fp16 GEMM A
__device__ __half g_stxh  [Bb * Ss * Dd];     // embedded short-term fp16
__device__ __half g_xWh   [Bb * Ss * G4];     // x@W+b fp16
__device__ __half g_hsh   [Bb * Ss * Dd];     // LSTM outputs fp16
__device__ __half g_qkvh  [Bb * Ss * 384];    // fused q|k|v fp16
__device__ __half g_atth  [Bb * Ss * Dd];     // attn out fp16 (Wo input)
__device__ float  g_stm   [Bb * Ss * Dd];     // MHA out (post-Wo) fp32
__device__ float  g_qvec  [Bb * Dd];
__device__ float  g_short [Bb * Dd];
__device__ float  g_long  [Bb * Dd];
__device__ __half g_Uh    [G4 * Dd];          // U^T fp16 [n=512][k=128]
__device__ __half g_Whr   [G4 * Dd];          // lstm_W^T fp16 [n=512][k=128]
__device__ __half g_Whqkv [384 * Dd];         // packed (Wq|Wk|Wv)^T [384][128]
__device__ __half g_Whor  [Dd * Dd];          // Wo^T [128][128]
__device__ __half g_Wh1   [Dd * UE];          // W1^T [128][256]
__device__ __half g_Whg   [Dd * G4];          // [Wu;Wsg;Wl]^T [128][512]
__device__ float  g_bg    [Dd];               // bu+bsg+bl

__device__ __forceinline__ float sigm(float x) { return 1.0f / (1.0f + __expf(-x)); }

__device__ __forceinline__ float tanh_mufu(float x) {
    float y;
    asm("tanh.approx.f32 %0, %1;" : "=f"(y) : "f"(x));
    return y;
}
__device__ __forceinline__ float sigm_mufu(float x) {
    return fmaf(0.5f, tanh_mufu(0.5f * x), 0.5f);
}

__device__ __forceinline__ void cp16(void* smem, const void* g) {
    uint32_t s = (uint32_t)__cvta_generic_to_shared(smem);
    asm volatile("cp.async.ca.shared.global [%0], [%1], 16;" :: "r"(s), "l"(g));
}

__device__ __forceinline__ void mma_f16(float* c, const uint32_t* a, const uint32_t* b) {
    asm volatile(
        "mma.sync.aligned.m16n8k16.row.col.f32.f16.f16.f32 "
        "{%0,%1,%2,%3}, {%4,%5,%6,%7}, {%8,%9}, {%0,%1,%2,%3};"
        : "+f"(c[0]), "+f"(c[1]), "+f"(c[2]), "+f"(c[3])
        : "r"(a[0]), "r"(a[1]), "r"(a[2]), "r"(a[3]), "r"(b[0]), "r"(b[1]));
}

__device__ __forceinline__ void ldsm_x4(uint32_t& r0, uint32_t& r1, uint32_t& r2,
                                        uint32_t& r3, uint32_t addr) {
    asm volatile("ldmatrix.sync.aligned.m8n8.x4.shared.b16 {%0,%1,%2,%3}, [%4];"
                 : "=r"(r0), "=r"(r1), "=r"(r2), "=r"(r3) : "r"(addr));
}

__device__ __forceinline__ void ldsm_x2(uint32_t& r0, uint32_t& r1, uint32_t addr) {
    asm volatile("ldmatrix.sync.aligned.m8n8.x2.shared.b16 {%0,%1}, [%2];"
                 : "=r"(r0), "=r"(r1) : "r"(addr));
}

// ---------------- 1) combined prep: gathers + all weight repacks ------------
__global__ void prep_kernel(const int* __restrict__ up, const int* __restrict__ stb,
                            const float* __restrict__ emb,
                            const float* __restrict__ Uw,
                            const float* __restrict__ lstm_W,
                            const float* __restrict__ Wq,
                            const float* __restrict__ Wk,
                            const float* __restrict__ Wv,
                            const float* __restrict__ Wo,
                            const float* __restrict__ W1,
                            const float* __restrict__ Wu,
                            const float* __restrict__ Wsg,
                            const float* __restrict__ Wl,
                            const float* __restrict__ bu,
                            const float* __restrict__ bsg,
                            const float* __restrict__ bl) {
    int idx = blockIdx.x * blockDim.x + threadIdx.x;
    if (idx < Bb * Ss * Dd) {
        int e = idx & (Ee - 1);
        int t = idx / Ee;
        int f = t & (Ff - 1);
        int bs = t / Ff;
        g_stxh[idx] = __float2half(emb[stb[bs * Ff + f] * Ee + e]);
        return;
    }
    int j = idx - Bb * Ss * Dd;
    if (j < Bb * UE) {
        int b = j / UE, r = j % UE;
        int u = r / Ee, e = r % Ee;
        float v = emb[up[b * Uu + u] * Ee + e];
        g_user_e[j] = v;
        g_gateAh[b * G4 + r] = __float2half(v);
        return;
    }
    j -= Bb * UE;
    if (j < G4 * Dd) {                         // U^T
        int n = j >> 7, k = j & 127;
        g_Uh[j] = __float2half(Uw[k * G4 + n]);
        return;
    }
    j -= G4 * Dd;
    if (j < G4 * Dd) {                         // lstm_W^T [512][128]
        int n = j >> 7, k = j & 127;
        g_Whr[j] = __float2half(lstm_W[k * G4 + n]);
        return;
    }
    j -= G4 * Dd;
    if (j < 384 * Dd) {                        // (Wq|Wk|Wv)^T [384][128]
        int n = j >> 7, k = j & 127;
        float v = (n < 128) ? Wq[k * Dd + n]
                : (n < 256) ? Wk[k * Dd + (n - 128)]
                            : Wv[k * Dd + (n - 256)];
        g_Whqkv[j] = __float2half(v);
        return;
    }
    j -= 384 * Dd;
    if (j < Dd * Dd) {                         // Wo^T [128][128]
        int n = j >> 7, k = j & 127;
        g_Whor[j] = __float2half(Wo[k * Dd + n]);
        return;
    }
    j -= Dd * Dd;
    if (j < Dd * UE) {                         // W1^T [128][256]
        int n = j >> 8, k = j & 255;
        g_Wh1[j] = __float2half(W1[k * Dd + n]);
        return;
    }
    j -= Dd * UE;
    if (j < Dd * G4) {                         // [Wu;Wsg;Wl]^T [128][512]
        int n = j >> 9, k = j & 511;
        float v = (k < 256) ? Wu[k * Dd + n]
                : (k < 384) ? Wsg[(k - 256) * Dd + n]
                            : Wl[(k - 384) * Dd + n];
        g_Whg[j] = __float2half(v);
        return;
    }
    j -= Dd * G4;
    if (j < Dd) g_bg[j] = bu[j] + bsg[j] + bl[j];
}

// ---------------- fp16 GEMM body (device-inlined) ---------------------------
// C = A[M,K] @ Wt[N,K]^T (+bias). Output: fp16 Ch if set, else fp32 C, else
// if mixout set: out = (1-sig(v))*g_long + sig(v)*g_short at flat index.
#define SH 40
#define TILE_H (128 * SH)
#define GEMM_SMEM_BYTES (4 * TILE_H * 2)

__device__ __forceinline__ void gemm_body(
    const __half* __restrict__ A, const __half* __restrict__ Wt,
    const float* __restrict__ bias, float* __restrict__ C,
    __half* __restrict__ Ch, float* __restrict__ mixout,
    int N, int K, int lda, int m0, int n0, __half* hsm) {
    __half* Asm = hsm;
    __half* Bsm = hsm + 2 * TILE_H;
    int tid = threadIdx.x;
    int lane = tid & 31, warp = tid >> 5;
    int wm = warp >> 1, wn = warp & 1;
    int gid = lane >> 2, tig = lane & 3;

    int arow = lane & 15, akofs = (lane >> 4) * 8;
    int bn = lane & 7, bkofs = ((lane >> 3) & 1) * 8;

    float c[2][8][4];
#pragma unroll
    for (int i = 0; i < 2; i++)
#pragma unroll
        for (int j = 0; j < 8; j++)
#pragma unroll
            for (int l = 0; l < 4; l++) c[i][j][l] = 0.f;

    {
#pragma unroll
        for (int i = 0; i < 2; i++) {
            int idx = tid + i * 256;
            int r = idx >> 2, c8 = (idx & 3) * 8;
            cp16(&Asm[r * SH + c8], &A[(size_t)(m0 + r) * lda + c8]);
        }
#pragma unroll
        for (int i = 0; i < 2; i++) {
            int idx = tid + i * 256;
            int r = idx >> 2, c8 = (idx & 3) * 8;
            cp16(&Bsm[r * SH + c8], &Wt[(size_t)(n0 + r) * K + c8]);
        }
        asm volatile("cp.async.commit_group;");
    }

    int cur = 0;
    for (int k0 = 0; k0 < K; k0 += 32) {
        if (k0 > 0) __syncthreads();
        if (k0 + 32 < K) {
            __half* As = Asm + (cur ^ 1) * TILE_H;
            __half* Bs = Bsm + (cur ^ 1) * TILE_H;
#pragma unroll
            for (int i = 0; i < 2; i++) {
                int idx = tid + i * 256;
                int r = idx >> 2, c8 = (idx & 3) * 8;
                cp16(&As[r * SH + c8], &A[(size_t)(m0 + r) * lda + k0 + 32 + c8]);
            }
#pragma unroll
            for (int i = 0; i < 2; i++) {
                int idx = tid + i * 256;
                int r = idx >> 2, c8 = (idx & 3) * 8;
                cp16(&Bs[r * SH + c8], &Wt[(size_t)(n0 + r) * K + k0 + 32 + c8]);
            }
            asm volatile("cp.async.commit_group;");
            asm volatile("cp.async.wait_group 1;");
        } else {
            asm volatile("cp.async.wait_group 0;");
        }
        __syncthreads();

        __half* As = Asm + cur * TILE_H;
        __half* Bs = Bsm + cur * TILE_H;
        uint32_t a_base = (uint32_t)__cvta_generic_to_shared(As);
        uint32_t b_base = (uint32_t)__cvta_generic_to_shared(Bs);
#pragma unroll
        for (int kt = 0; kt < 2; kt++) {
            uint32_t a[2][4];
#pragma unroll
            for (int mt = 0; mt < 2; mt++) {
                int mr = wm * 32 + mt * 16 + arow;
                ldsm_x4(a[mt][0], a[mt][1], a[mt][2], a[mt][3],
                        a_base + (mr * SH + kt * 16 + akofs) * 2);
            }
#pragma unroll
            for (int nt = 0; nt < 8; nt++) {
                uint32_t b[2];
                int nr = wn * 64 + nt * 8 + bn;
                ldsm_x2(b[0], b[1], b_base + (nr * SH + kt * 16 + bkofs) * 2);
#pragma unroll
                for (int mt = 0; mt < 2; mt++)
                    mma_f16(c[mt][nt], a[mt], b);
            }
        }
        cur ^= 1;
    }

#pragma unroll
    for (int mt = 0; mt < 2; mt++) {
        int row = m0 + wm * 32 + mt * 16 + gid;
#pragma unroll
        for (int nt = 0; nt < 8; nt++) {
            int col = n0 + wn * 64 + nt * 8 + 2 * tig;
            float bx = 0.f, by = 0.f;
            if (bias) { bx = bias[col]; by = bias[col + 1]; }
            float v00 = c[mt][nt][0] + bx, v01 = c[mt][nt][1] + by;
            float v10 = c[mt][nt][2] + bx, v11 = c[mt][nt][3] + by;
            if (mixout) {
                size_t i0 = (size_t)row * N + col;
                size_t i1 = (size_t)(row + 8) * N + col;
                float g00 = sigm(v00), g01 = sigm(v01);
                float g10 = sigm(v10), g11 = sigm(v11);
                mixout[i0]     = (1.f - g00) * g_long[i0]     + g00 * g_short[i0];
                mixout[i0 + 1] = (1.f - g01) * g_long[i0 + 1] + g01 * g_short[i0 + 1];
                mixout[i1]     = (1.f - g10) * g_long[i1]     + g10 * g_short[i1];
                mixout[i1 + 1] = (1.f - g11) * g_long[i1 + 1] + g11 * g_short[i1 + 1];
            } else if (Ch) {
                *(__half2*)&Ch[(size_t)row * N + col] = __floats2half2_rn(v00, v01);
                *(__half2*)&Ch[(size_t)(row + 8) * N + col] = __floats2half2_rn(v10, v11);
            } else {
                *(float2*)&C[(size_t)row * N + col] = make_float2(v00, v01);
                *(float2*)&C[(size_t)(row + 8) * N + col] = make_float2(v10, v11);
            }
        }
    }
}

__global__ __launch_bounds__(256, 2) void gemm_f16(
    const __half* __restrict__ A, const __half* __restrict__ Wt,
    const float* __restrict__ bias, float* __restrict__ C,
    __half* __restrict__ Ch, float* __restrict__ mixout,
    int N, int K, int lda) {
    extern __shared__ __half hsm[];
    gemm_body(A, Wt, bias, C, Ch, mixout, N, K, lda,
              blockIdx.y * 128, blockIdx.x * 128, hsm);
}

// ---------------- longterm body (dynamic smem) ------------------------------
#define LT_STRIDE 36
__device__ void longterm_body(int bi, const int* __restrict__ ltb,
                              const float* __restrict__ emb,
                              const float* __restrict__ Wt,
                              const float* __restrict__ bt, float* fsm) {
    int b = bi >> 2, fi = bi & 3;
    float* vecs = fsm;                          // [200][36] = 28800 B
    float* uv   = fsm + Ll * LT_STRIDE;         // 32 floats (16B-aligned)
    float* sc   = uv + Ee;                      // 200
    float* part = sc + Ll + 24;                 // [8][32] (pad sc to 224)
    float* red  = part + 256;                   // 256
    int*   ids  = (int*)(red + 256);            // 200
    int t = threadIdx.x;
    if (t < Ll) ids[t] = ltb[(b * Ll + t) * Ff + fi];
    __syncthreads();
    for (int idx = t; idx < Ll * 8; idx += 256) {
        int l = idx >> 3, q4 = idx & 7;
        *(float4*)&vecs[l * LT_STRIDE + q4 * 4] = *(const float4*)&emb[ids[l] * Ee + q4 * 4];
    }
    {
        int e = t & 31, g = t >> 5;
        float a = 0.f;
        for (int k = g * 32; k < g * 32 + 32; k++)
            a += g_user_e[b * UE + k] * Wt[(fi * UE + k) * Ee + e];
        part[g * Ee + e] = a;
    }
    __syncthreads();
    if (t < Ee) {
        float a = bt[fi * Ee + t];
        for (int g = 0; g < 8; g++) a += part[g * Ee + t];
        uv[t] = a;
    }
    __syncthreads();
    if (t < Ll) {
        int mid = ids[t];
        bool keep = true;
        for (int j = 0; j < t; j++) if (ids[j] == mid) { keep = false; break; }
        float a = 0.f;
#pragma unroll
        for (int i = 0; i < 8; i++) {
            float4 v4 = *(float4*)&vecs[t * LT_STRIDE + i * 4];
            float4 u4 = *(float4*)&uv[i * 4];
            a += v4.x * u4.x + v4.y * u4.y + v4.z * u4.z + v4.w * u4.w;
        }
        sc[t] = keep ? a : NEGV;
    }
    __syncthreads();
    red[t] = (t < Ll) ? sc[t] : -3.4e38f;
    __syncthreads();
    for (int ofs = 128; ofs >= 1; ofs >>= 1) {
        if (t < ofs) red[t] = fmaxf(red[t], red[t + ofs]);
        __syncthreads();
    }
    float mx = red[0];
    __syncthreads();
    float ev = (t < Ll) ? __expf(sc[t] - mx) : 0.f;
    if (t < Ll) sc[t] = ev;
    red[t] = ev;
    __syncthreads();
    for (int ofs = 128; ofs >= 1; ofs >>= 1) {
        if (t < ofs) red[t] += red[t + ofs];
        __syncthreads();
    }
    float inv = 1.f / red[0];
    __syncthreads();
    {
        int e = t & 31, g = t >> 5;
        float a = 0.f;
        for (int l = g; l < Ll; l += 8) a += sc[l] * vecs[l * LT_STRIDE + e];
        part[g * Ee + e] = a;
    }
    __syncthreads();
    if (t < Ee) {
        float a = 0.f;
        for (int g = 0; g < 8; g++) a += part[g * Ee + t];
        float r = a * inv;
        g_long[b * Dd + fi * Ee + t] = r;
        g_gateAh[b * G4 + 384 + fi * Ee + t] = __float2half(r);
    }
}

// ---------------- fused A: xW GEMM (1600) + longterm (4096) + qvec (8) ------
#define XW_BLOCKS 1600
#define LT_BLOCKS 4096
__global__ __launch_bounds__(256, 2) void fused_a_kernel(
    const int* __restrict__ ltb, const float* __restrict__ emb,
    const float* __restrict__ Wt, const float* __restrict__ bt,
    const float* __restrict__ lstm_b, const float* __restrict__ b1) {
    extern __shared__ __half hsm[];
    int bid = blockIdx.x;
    if (bid < XW_BLOCKS) {
        gemm_body(g_stxh, g_Whr, lstm_b, nullptr, g_xWh, nullptr,
                  G4, Dd, Dd, (bid >> 2) * 128, (bid & 3) * 128, hsm);
    } else if (bid < XW_BLOCKS + LT_BLOCKS) {
        longterm_body(bid - XW_BLOCKS, ltb, emb, Wt, bt, (float*)hsm);
    } else {
        gemm_body(g_gateAh, g_Wh1, b1, g_qvec, nullptr, nullptr,
                  Dd, UE, G4, (bid - XW_BLOCKS - LT_BLOCKS) * 128, 0, hsm);
    }
}

// ---------------- 3) LSTM: fp16 mma, 16 warps (xW + hs fp16) ----------------
#define UT_STRIDE 136
#define HB_STRIDE 136
#define LSTM_ROWS 8
#define LSTM_SMEM_BYTES (G4 * UT_STRIDE * 2 + 2 * 16 * HB_STRIDE * 2)

__global__ __launch_bounds__(512, 1) void lstm_mma_kernel(
    const __half* __restrict__ xW, __half* __restrict__ hs) {
    extern __shared__ __align__(16) char smem_raw[];
    __half* Ut  = (__half*)smem_raw;                          // [512][136]
    __half* hb0 = (__half*)(smem_raw + G4 * UT_STRIDE * 2);   // [16][136]
    __half* hb1 = hb0 + 16 * HB_STRIDE;                       // [16][136]

    int tid = threadIdx.x;
    int lane = tid & 31, warp = tid >> 5;
    int b0 = blockIdx.x * LSTM_ROWS;

    for (int i = tid; i < G4 * Dd / 8; i += 512) {
        int n = i >> 4, c = (i & 15) * 8;
        cp16(&Ut[n * UT_STRIDE + c], &g_Uh[n * Dd + c]);
    }
    for (int i = tid; i < 2 * 16 * HB_STRIDE; i += 512) hb0[i] = __float2half(0.f);
    asm volatile("cp.async.commit_group;");
    asm volatile("cp.async.wait_group 0;");
    __syncthreads();

    int arow = lane & 15;
    int akofs = (lane >> 4) * 8;
    uint32_t aAddr0 = (uint32_t)__cvta_generic_to_shared(hb0) +
                      (arow * HB_STRIDE + akofs) * 2;
    uint32_t aAddr1 = (uint32_t)__cvta_generic_to_shared(hb1) +
                      (arow * HB_STRIDE + akofs) * 2;

    uint32_t ut_base = (uint32_t)__cvta_generic_to_shared(Ut);
    int bn = lane & 7;
    int bkofs = ((lane >> 3) & 1) * 8;
    uint32_t bf[8][4][2];
#pragma unroll
    for (int g = 0; g < 4; g++) {
        uint32_t base = ut_base +
            ((g * 128 + warp * 8 + bn) * UT_STRIDE + bkofs) * 2;
#pragma unroll
        for (int kt = 0; kt < 8; kt++)
            ldsm_x2(bf[kt][g][0], bf[kt][g][1], base + kt * 32);
    }

    int gid = lane >> 2, tig = lane & 3;
    int col0 = warp * 8 + 2 * tig;
    const __half* xrow = xW + (size_t)((b0 + gid) * Ss) * G4 + col0;
    __half* hsrow = hs + (size_t)((b0 + gid) * Ss) * Dd + col0;

    float cc0 = 0.f, cc1 = 0.f;
    float2 xg_c[4], xg_n[4];
#pragma unroll
    for (int g = 0; g < 4; g++) {
        xg_c[g] = __half22float2(*(const __half2*)&xrow[g * 128]);
        xg_n[g] = xg_c[g];
    }

    int p = 0;
    for (int step = 0; step < Ss; step++) {
        if (step + 1 < Ss) {
            const __half* xb = xrow + (step + 1) * G4;
#pragma unroll
            for (int g = 0; g < 4; g++)
                xg_n[g] = __half22float2(*(const __half2*)&xb[g * 128]);
        }

        float acc[4][4];
#pragma unroll
        for (int g = 0; g < 4; g++)
#pragma unroll
            for (int j = 0; j < 4; j++) acc[g][j] = 0.f;
        uint32_t aAddr = p ? aAddr1 : aAddr0;
#pragma unroll
        for (int kt = 0; kt < 8; kt++) {
            uint32_t a[4];
            ldsm_x4(a[0], a[1], a[2], a[3], aAddr + kt * 32);
#pragma unroll
            for (int g = 0; g < 4; g++)
                mma_f16(acc[g], a, bf[kt][g]);
        }

        float iv0 = sigm_mufu(acc[0][0] + xg_c[0].x);
        float iv1 = sigm_mufu(acc[0][1] + xg_c[0].y);
        float fv0 = sigm_mufu(acc[1][0] + xg_c[1].x);
        float fv1 = sigm_mufu(acc[1][1] + xg_c[1].y);
        float gv0 = tanh_mufu(acc[2][0] + xg_c[2].x);
        float gv1 = tanh_mufu(acc[2][1] + xg_c[2].y);
        float ov0 = sigm_mufu(acc[3][0] + xg_c[3].x);
        float ov1 = sigm_mufu(acc[3][1] + xg_c[3].y);
        cc0 = fv0 * cc0 + iv0 * gv0;
        cc1 = fv1 * cc1 + iv1 * gv1;
        float h0 = ov0 * tanh_mufu(cc0);
        float h1 = ov1 * tanh_mufu(cc1);

        __half2 h01 = __floats2half2_rn(h0, h1);
        __half* hw = p ? hb0 : hb1;
        *(__half2*)&hw[gid * HB_STRIDE + col0] = h01;
        *(__half2*)&hsrow[step * Dd] = h01;
        __syncthreads();
        p ^= 1;
#pragma unroll
        for (int g = 0; g < 4; g++) xg_c[g] = xg_n[g];
    }
}

// ---------------- 4) MHA core (qkv fp16 in, att fp16 out) -------------------
#define QK_STRIDE 36
__global__ __launch_bounds__(128) void mha_kernel() {
    int bh = blockIdx.x;
    int b = bh >> 2, h = bh & 3;
    __shared__ float qs[Ss][QK_STRIDE], ks[Ss][QK_STRIDE], vs[Ss][QK_STRIDE];
    __shared__ float sc[Ss][52];
    int t = threadIdx.x;

    for (int idx = t; idx < 600; idx += 128) {
        int which = idx / 200;
        int rem = idx - which * 200;
        int s = rem >> 2, c8 = (rem & 3) * 8;
        const __half2* src = (const __half2*)&g_qkvh[(b * Ss + s) * 384 + which * 128 + h * Ee + c8];
        float* dst = (which == 0) ? &qs[s][c8]
                   : (which == 1) ? &ks[s][c8] : &vs[s][c8];
#pragma unroll
        for (int i = 0; i < 4; i++) {
            float2 v = __half22float2(src[i]);
            dst[2 * i] = v.x; dst[2 * i + 1] = v.y;
        }
    }
    __syncthreads();

    const float scale = 0.17677669529663687f;
    if (t < 100) {
        int r = t >> 1;
        int c0 = (t & 1) * 25;
        float4 q[8];
#pragma unroll
        for (int i = 0; i < 8; i++) q[i] = *(float4*)&qs[r][i * 4];
        for (int c = c0; c < c0 + 25; c++) {
            float a = 0.f;
#pragma unroll
            for (int i = 0; i < 8; i++) {
                float4 k4 = *(float4*)&ks[c][i * 4];
                a += q[i].x * k4.x + q[i].y * k4.y + q[i].z * k4.z + q[i].w * k4.w;
            }
            sc[r][c] = a * scale;
        }
    }
    __syncthreads();
    if (t < Ss) {
        float mx = -3.4e38f;
        for (int c = 0; c < Ss; c++) mx = fmaxf(mx, sc[t][c]);
        float sm = 0.f;
        for (int c = 0; c < Ss; c++) { float e = __expf(sc[t][c] - mx); sc[t][c] = e; sm += e; }
        float inv = 1.f / sm;
        for (int c = 0; c < Ss; c++) sc[t][c] *= inv;
    }
    __syncthreads();
    int q4 = t & 7;
    for (int s = t >> 3; s < Ss; s += 16) {
        float4 acc = make_float4(0.f, 0.f, 0.f, 0.f);
        for (int c = 0; c < Ss; c++) {
            float a = sc[s][c];
            float4 v4 = *(float4*)&vs[c][q4 * 4];
            acc.x += a * v4.x; acc.y += a * v4.y;
            acc.z += a * v4.z; acc.w += a * v4.w;
        }
        __half* dst = &g_atth[(b * Ss + s) * Dd + h * Ee + q4 * 4];
        *(__half2*)&dst[0] = __floats2half2_rn(acc.x, acc.y);
        *(__half2*)&dst[2] = __floats2half2_rn(acc.z, acc.w);
    }
}

// ---------------- 5) short-term pooling -------------------------------------
__global__ __launch_bounds__(128) void shortpool_kernel() {
    int b = blockIdx.x;
    __shared__ float qv[Dd];
    __shared__ float sc[64];
    __shared__ float red4[4];
    int t = threadIdx.x;
    qv[t] = g_qvec[b * Dd + t];
    if (t >= Ss && t < 64) sc[t] = -3.4e38f;
    __syncthreads();
    if (t < Ss) {
        const float* row = &g_stm[(b * Ss + t) * Dd];
        float a = 0.f;
        for (int k = 0; k < Dd; k++) a += row[k] * qv[k];
        sc[t] = a;
    }
    __syncthreads();
    if (t < 64) {
        float v = sc[t];
#pragma unroll
        for (int ofs = 16; ofs >= 1; ofs >>= 1)
            v = fmaxf(v, __shfl_xor_sync(0xFFFFFFFFu, v, ofs));
        if ((t & 31) == 0) red4[t >> 5] = v;
    }
    __syncthreads();
    float mx = fmaxf(red4[0], red4[1]);
    float ev = (t < Ss) ? __expf(sc[t] - mx) : 0.f;
    if (t < 64) sc[t] = ev;
    __syncthreads();
    if (t < 64) {
        float v = sc[t];
#pragma unroll
        for (int ofs = 16; ofs >= 1; ofs >>= 1)
            v += __shfl_xor_sync(0xFFFFFFFFu, v, ofs);
        if ((t & 31) == 0) red4[2 + (t >> 5)] = v;
    }
    __syncthreads();
    float inv = 1.f / (red4[2] + red4[3]);
    float a = 0.f;
    for (int s = 0; s < Ss; s++) a += sc[s] * g_stm[(b * Ss + s) * Dd + t];
    float r = a * inv;
    g_short[b * Dd + t] = r;
    g_gateAh[b * G4 + 256 + t] = __float2half(r);
}

// ---------------- host ------------------------------------------------------
static void* symv(const void* s) {
    void* p = nullptr;
    cudaGetSymbolAddress(&p, s);
    return p;
}

extern "C" void kernel_launch(void* const* d_in, const int* in_sizes, int n_in,
                              void* d_out, int out_size) {
    const int*   up     = (const int*)d_in[0];
    const int*   stb    = (const int*)d_in[1];
    const int*   ltb    = (const int*)d_in[2];
    const float* emb    = (const float*)d_in[3];
    const float* lstm_W = (const float*)d_in[4];
    const float* lstm_U = (const float*)d_in[5];
    const float* lstm_b = (const float*)d_in[6];
    const float* Wq     = (const float*)d_in[7];
    const float* Wk     = (const float*)d_in[8];
    const float* Wv     = (const float*)d_in[9];
    const float* Wo     = (const float*)d_in[10];
    const float* W1     = (const float*)d_in[11];
    const float* b1     = (const float*)d_in[12];
    const float* Wt     = (const float*)d_in[13];
    const float* bt     = (const float*)d_in[14];
    const float* Wu     = (const float*)d_in[15];
    const float* bu     = (const float*)d_in[16];
    const float* Wsg    = (const float*)d_in[17];
    const float* bsg    = (const float*)d_in[18];
    const float* Wl     = (const float*)d_in[19];
    const float* bl     = (const float*)d_in[20];
    float* out = (float*)d_out;

    __half* p_gateAh = (__half*)symv(g_gateAh);
    __half* p_xWh    = (__half*)symv(g_xWh);
    __half* p_hsh    = (__half*)symv(g_hsh);
    __half* p_qkvh   = (__half*)symv(g_qkvh);
    __half* p_atth   = (__half*)symv(g_atth);
    float*  p_stm    = (float*)symv(g_stm);
    __half* p_Whqkv  = (__half*)symv(g_Whqkv);
    __half* p_Whor   = (__half*)symv(g_Whor);
    __half* p_Whg    = (__half*)symv(g_Whg);
    float*  p_bg     = (float*)symv(g_bg);

    const int MBS = Bb * Ss;  // 51200

    cudaFuncSetAttribute(lstm_mma_kernel,
                         cudaFuncAttributeMaxDynamicSharedMemorySize,
                         LSTM_SMEM_BYTES);
    cudaFuncSetAttribute(gemm_f16,
                         cudaFuncAttributeMaxDynamicSharedMemorySize,
                         GEMM_SMEM_BYTES);
    cudaFuncSetAttribute(fused_a_kernel,
                         cudaFuncAttributeMaxDynamicSharedMemorySize,
                         GEMM_SMEM_BYTES);

    // 1) combined prep (gathers + all repacks)
    {
        int total = Bb * Ss * Dd + Bb * UE + G4 * Dd + G4 * Dd + 384 * Dd
                  + Dd * Dd + Dd * UE + Dd * G4 + Dd;
        prep_kernel<<<(total + 255) / 256, 256>>>(
            up, stb, emb, lstm_U, lstm_W, Wq, Wk, Wv, Wo, W1, Wu, Wsg, Wl,
            bu, bsg, bl);
    }
    // 2) fused A: xW GEMM + longterm + qvec GEMM (all depend only on prep)
    fused_a_kernel<<<XW_BLOCKS + LT_BLOCKS + Bb / 128, 256, GEMM_SMEM_BYTES>>>(
        ltb, emb, Wt, bt, lstm_b, b1);
    // 3) LSTM recurrence
    lstm_mma_kernel<<<Bb / LSTM_ROWS, 512, LSTM_SMEM_BYTES>>>(p_xWh, p_hsh);
    // 4) fused QKV projection -> fp16
    gemm_f16<<<dim3(384 / 128, MBS / 128), 256, GEMM_SMEM_BYTES>>>(
        p_hsh, p_Whqkv, nullptr, nullptr, p_qkvh, nullptr, 384, Dd, Dd);
    // 5) attention core + output projection (stm fp32)
    mha_kernel<<<Bb * Ff, 128>>>();
    gemm_f16<<<dim3(Dd / 128, MBS / 128), 256, GEMM_SMEM_BYTES>>>(
        p_atth, p_Whor, nullptr, p_stm, nullptr, nullptr, Dd, Dd, Dd);
    // 6) short-term pooling
    shortpool_kernel<<<Bb, 128>>>();
    // 7) gate preact GEMM with fused sigmoid-mix epilogue -> out
    gemm_f16<<<dim3(Dd / 128, Bb / 128), 256, GEMM_SMEM_BYTES>>>(
        p_gateAh, p_Whg, p_bg, nullptr, nullptr, out, Dd, G4, G4);
}